// round 3
// baseline (speedup 1.0000x reference)
#include <cuda_runtime.h>
#include <math.h>

#define BB 64
#define TT 1024
#define II 512
#define HH 1024
#define GG (4*HH)   // 4096
#define TOPN 256
#define NCTA 128

// Scratch (allocation-free rule: __device__ globals)
__device__ float g_xg[(size_t)BB*TT*GG];   // 1 GiB: x@Wi^T + bi, [B*T][4H]
__device__ float g_tg[BB*HH];              // topic gate bias
__device__ float g_hb[2][BB*HH];           // double-buffered h state
__device__ unsigned g_bar_count = 0;
__device__ volatile unsigned g_bar_gen = 0;

// Packed fp32x2 FMA (Blackwell): d = a*b + d per 32-bit half.
__device__ __forceinline__ float2 ffma2(float2 d, float2 a, float2 b) {
    asm("fma.rn.f32x2 %0, %1, %2, %0;"
        : "+l"(reinterpret_cast<unsigned long long&>(d))
        : "l"(reinterpret_cast<unsigned long long&>(a)),
          "l"(reinterpret_cast<unsigned long long&>(b)));
    return d;
}

// ---------------------------------------------------------------- tg = topic @ Wt^T + bt
__global__ void k_tg(const float* __restrict__ topic, const float* __restrict__ Wt,
                     const float* __restrict__ bt) {
    __shared__ float ts[TOPN];
    int b = blockIdx.y;
    int j = blockIdx.x * 128 + threadIdx.x;
    ts[threadIdx.x]       = topic[b*TOPN + threadIdx.x];
    ts[threadIdx.x + 128] = topic[b*TOPN + threadIdx.x + 128];
    __syncthreads();
    const float4* w = (const float4*)(Wt + (size_t)j * TOPN);
    float acc = bt[j];
#pragma unroll
    for (int k = 0; k < TOPN/4; k++) {
        float4 wv = w[k];
        acc += ts[4*k+0]*wv.x + ts[4*k+1]*wv.y + ts[4*k+2]*wv.z + ts[4*k+3]*wv.w;
    }
    g_tg[b*HH + j] = acc;
}

// ---------------------------------------------------------------- xg = x @ Wi^T + bi
// C[65536,4096] = x[65536,512] @ Wi[4096,512]^T. 128x128 tile, 256 thr,
// thread tile 8(M, packed as 4 f32x2 pairs) x 8(N). W pre-duplicated in smem.
__global__ void __launch_bounds__(256) k_xg(const float* __restrict__ x,
                                            const float* __restrict__ Wi,
                                            const float* __restrict__ bi) {
    __shared__ float  xs[16][132];     // [k][m] scalar
    __shared__ float2 ws2[16][130];    // [k][n] duplicated (w,w)
    int m0 = blockIdx.y * 128;
    int n0 = blockIdx.x * 128;
    int tid = threadIdx.x;
    int tr = tid >> 4;     // 0..15 -> m rows tr*4..+3 and 64+tr*4..+3
    int tc = tid & 15;     // 0..15 -> n cols tc*4..+3 and 64+tc*4..+3
    float2 acc2[4][8];
#pragma unroll
    for (int p = 0; p < 4; p++)
#pragma unroll
        for (int v = 0; v < 8; v++) acc2[p][v] = make_float2(0.f, 0.f);

    for (int k0 = 0; k0 < II; k0 += 16) {
#pragma unroll
        for (int i = 0; i < 8; i++) {
            int lin = tid + i*256;
            int r = lin >> 4, kk = lin & 15;
            xs[kk][r] = x[(size_t)(m0 + r)*II + k0 + kk];
            float w = Wi[(size_t)(n0 + r)*II + k0 + kk];
            ws2[kk][r] = make_float2(w, w);
        }
        __syncthreads();
#pragma unroll
        for (int kk = 0; kk < 16; kk++) {
            float4 aA = *(const float4*)&xs[kk][tr*4];
            float4 aB = *(const float4*)&xs[kk][64 + tr*4];
            float2 ap[4] = { make_float2(aA.x, aA.y), make_float2(aA.z, aA.w),
                             make_float2(aB.x, aB.y), make_float2(aB.z, aB.w) };
            float4 wA = *(const float4*)&ws2[kk][tc*4];
            float4 wB = *(const float4*)&ws2[kk][tc*4 + 2];
            float4 wC = *(const float4*)&ws2[kk][64 + tc*4];
            float4 wD = *(const float4*)&ws2[kk][64 + tc*4 + 2];
            float2 wd[8] = { make_float2(wA.x, wA.y), make_float2(wA.z, wA.w),
                             make_float2(wB.x, wB.y), make_float2(wB.z, wB.w),
                             make_float2(wC.x, wC.y), make_float2(wC.z, wC.w),
                             make_float2(wD.x, wD.y), make_float2(wD.z, wD.w) };
#pragma unroll
            for (int p = 0; p < 4; p++)
#pragma unroll
                for (int v = 0; v < 8; v++)
                    acc2[p][v] = ffma2(acc2[p][v], ap[p], wd[v]);
        }
        __syncthreads();
    }
    float bv[8];
#pragma unroll
    for (int v = 0; v < 8; v++) {
        int n = n0 + ((v < 4) ? (tc*4 + v) : (64 + tc*4 + v - 4));
        bv[v] = bi[n];
    }
#pragma unroll
    for (int p = 0; p < 4; p++) {
        int m = m0 + ((p < 2) ? (tr*4 + 2*p) : (64 + tr*4 + 2*(p - 2)));
#pragma unroll
        for (int v = 0; v < 8; v++) {
            int n = n0 + ((v < 4) ? (tc*4 + v) : (64 + tc*4 + v - 4));
            g_xg[(size_t)m*GG + n]       = acc2[p][v].x + bv[v];
            g_xg[(size_t)(m+1)*GG + n]   = acc2[p][v].y + bv[v];
        }
    }
}

// ---------------------------------------------------------------- grid barrier
__device__ __forceinline__ void grid_bar() {
    __syncthreads();
    if (threadIdx.x == 0) {
        __threadfence();
        unsigned gen = g_bar_gen;
        if (atomicAdd(&g_bar_count, 1u) == NCTA - 1) {
            g_bar_count = 0;
            __threadfence();
            g_bar_gen = gen + 1;
        } else {
            while (g_bar_gen == gen) __nanosleep(32);
            __threadfence();
        }
    }
    __syncthreads();
}

// ---------------------------------------------------------------- persistent recurrence
// 128 CTAs x 256 thr, all co-resident. CTA c owns h-columns j0=c*8..+7, all 4
// gates (CTA-local N tile of 32), all 64 batches. One grid barrier per step.
__global__ void __launch_bounds__(256) k_rec(const float* __restrict__ Wh,
                                             const float* __restrict__ bh,
                                             const float* __restrict__ h0,
                                             const float* __restrict__ c0,
                                             float* __restrict__ out) {
    __shared__ float  hs[16][68];      // [k][b]
    __shared__ float2 wdup[16][34];    // [k][n-local] duplicated (w,w)
    __shared__ float  ga[32][66];      // [n-local][b] gate values
    const int tid = threadIdx.x;
    const int c = blockIdx.x;
    const int j0 = c * 8;

    // stage h0 into buffer 0
#pragma unroll
    for (int i = 0; i < 2; i++) {
        int idx = c*512 + tid + i*256;
        g_hb[0][idx] = h0[idx];
    }

    // elementwise cell ownership: cells e = 2*tid, 2*tid+1 -> (b_e, jl_e), (b_e, jl_e+1)
    const int b_e  = tid >> 2;
    const int jl_e = (tid & 3) * 2;
    const int jg0  = j0 + jl_e;
    float cr0 = c0[b_e*HH + jg0];
    float cr1 = c0[b_e*HH + jg0 + 1];
    const float tg0 = g_tg[b_e*HH + jg0];
    const float tg1 = g_tg[b_e*HH + jg0 + 1];
    float bhv[4][2];
#pragma unroll
    for (int g = 0; g < 4; g++) {
        bhv[g][0] = bh[g*HH + jg0];
        bhv[g][1] = bh[g*HH + jg0 + 1];
    }

    // GEMM thread mapping
    const int mg = tid >> 4;           // 0..15, m = mg*4..+3
    const int np = tid & 15;           // 0..15, n-local = np*2, np*2+1
    // Wh loader rows for this thread (loader: kk=tid&15, nl=tid>>4 and +16)
    const int lkk = tid & 15;
    const int lnl = tid >> 4;
    const int row0 = ((lnl      >> 3) * HH) + j0 + (lnl & 7);
    const int row1 = (((lnl+16) >> 3) * HH) + j0 + ((lnl+16) & 7);
    const float* wp0 = Wh + (size_t)row0 * HH;
    const float* wp1 = Wh + (size_t)row1 * HH;

    grid_bar();   // h0 visible everywhere

    for (int t = 0; t < TT; t++) {
        const int rb = t & 1, wb = rb ^ 1;
        const float* hbase = g_hb[rb];
        float2 acc[2][2];
        acc[0][0] = acc[0][1] = acc[1][0] = acc[1][1] = make_float2(0.f, 0.f);

        for (int k0 = 0; k0 < HH; k0 += 16) {
#pragma unroll
            for (int i = 0; i < 4; i++)
                hs[lkk][lnl + i*16] = __ldcg(&hbase[(lnl + i*16)*HH + k0 + lkk]);
            {
                float w0 = __ldg(wp0 + k0 + lkk);
                float w1 = __ldg(wp1 + k0 + lkk);
                wdup[lkk][lnl]      = make_float2(w0, w0);
                wdup[lkk][lnl + 16] = make_float2(w1, w1);
            }
            __syncthreads();
#pragma unroll
            for (int kk = 0; kk < 16; kk++) {
                float4 av = *(const float4*)&hs[kk][mg*4];
                float4 wv = *(const float4*)&wdup[kk][np*2];
                float2 a0 = make_float2(av.x, av.y), a1 = make_float2(av.z, av.w);
                float2 w0 = make_float2(wv.x, wv.y), w1 = make_float2(wv.z, wv.w);
                acc[0][0] = ffma2(acc[0][0], a0, w0);
                acc[1][0] = ffma2(acc[1][0], a1, w0);
                acc[0][1] = ffma2(acc[0][1], a0, w1);
                acc[1][1] = ffma2(acc[1][1], a1, w1);
            }
            __syncthreads();
        }

        // scatter gates to smem: ga[n-local][b]
        *(float2*)&ga[np*2    ][mg*4]     = acc[0][0];
        *(float2*)&ga[np*2    ][mg*4 + 2] = acc[1][0];
        *(float2*)&ga[np*2 + 1][mg*4]     = acc[0][1];
        *(float2*)&ga[np*2 + 1][mg*4 + 2] = acc[1][1];
        __syncthreads();

        // elementwise for 2 owned cells
        {
            const size_t xb = ((size_t)b_e*TT + t)*GG + jg0;
            float gi0 = ga[     jl_e][b_e] + g_xg[xb           ] + bhv[0][0] + tg0;
            float gf0 = ga[ 8 + jl_e][b_e] + g_xg[xb +     HH  ] + bhv[1][0] + tg0;
            float gc0 = ga[16 + jl_e][b_e] + g_xg[xb + 2*(size_t)HH] + bhv[2][0];
            float go0 = ga[24 + jl_e][b_e] + g_xg[xb + 3*(size_t)HH] + bhv[3][0];
            float gi1 = ga[     jl_e + 1][b_e] + g_xg[xb + 1         ] + bhv[0][1] + tg1;
            float gf1 = ga[ 8 + jl_e + 1][b_e] + g_xg[xb + 1 +   HH  ] + bhv[1][1] + tg1;
            float gc1 = ga[16 + jl_e + 1][b_e] + g_xg[xb + 1 + 2*(size_t)HH] + bhv[2][1];
            float go1 = ga[24 + jl_e + 1][b_e] + g_xg[xb + 1 + 3*(size_t)HH] + bhv[3][1];

            float ig0 = 1.f/(1.f + expf(-gi0)), fg0 = 1.f/(1.f + expf(-gf0));
            float cg0 = tanhf(gc0),             og0 = 1.f/(1.f + expf(-go0));
            float cy0 = fg0*cr0 + ig0*cg0;
            float hy0 = og0 * tanhf(cy0);
            float ig1 = 1.f/(1.f + expf(-gi1)), fg1 = 1.f/(1.f + expf(-gf1));
            float cg1 = tanhf(gc1),             og1 = 1.f/(1.f + expf(-go1));
            float cy1 = fg1*cr1 + ig1*cg1;
            float hy1 = og1 * tanhf(cy1);
            cr0 = cy0; cr1 = cy1;

            g_hb[wb][b_e*HH + jg0]     = hy0;
            g_hb[wb][b_e*HH + jg0 + 1] = hy1;
            size_t ob = ((size_t)b_e*TT + t)*HH + jg0;
            out[ob]     = hy0;
            out[ob + 1] = hy1;
            if (t == TT - 1) {
                const size_t HN = (size_t)BB*TT*HH;
                out[HN + b_e*HH + jg0]     = hy0;
                out[HN + b_e*HH + jg0 + 1] = hy1;
                out[HN + (size_t)BB*HH + b_e*HH + jg0]     = cy0;
                out[HN + (size_t)BB*HH + b_e*HH + jg0 + 1] = cy1;
            }
        }
        if (t < TT - 1) grid_bar();
    }
}

// ----------------------------------------------------------------
extern "C" void kernel_launch(void* const* d_in, const int* in_sizes, int n_in,
                              void* d_out, int out_size) {
    const float* x     = (const float*)d_in[0];
    const float* h0    = (const float*)d_in[1];
    const float* c0    = (const float*)d_in[2];
    const float* topic = (const float*)d_in[3];
    const float* Wi    = (const float*)d_in[4];
    const float* bi    = (const float*)d_in[5];
    const float* Wh    = (const float*)d_in[6];
    const float* bh    = (const float*)d_in[7];
    const float* Wt    = (const float*)d_in[8];
    const float* bt    = (const float*)d_in[9];
    float* out = (float*)d_out;

    k_tg<<<dim3(8, 64), 128>>>(topic, Wt, bt);
    k_xg<<<dim3(GG/128, (BB*TT)/128), 256>>>(x, Wi, bi);   // (32, 512)
    k_rec<<<NCTA, 256>>>(Wh, bh, h0, c0, out);
}

// round 4
// speedup vs baseline: 1.0537x; 1.0537x over previous
#include <cuda_runtime.h>
#include <math.h>

#define BB 64
#define TT 1024
#define II 512
#define HH 1024
#define GG (4*HH)   // 4096
#define TOPN 256
#define NCTA 128

// Dynamic smem carve for k_rec
#define SM_WP_BYTES (1024*16*8)          // wpairs[1024][16] float2 = 131072
#define SM_HS_BYTES (2*16*66*8)          // hs2[2][16][66] float2 = 16896
#define SM_GA_BYTES (32*66*4)            // ga[32][66] float = 8448
#define SM_REC_TOTAL (SM_WP_BYTES + SM_HS_BYTES + SM_GA_BYTES)

// Scratch (allocation-free rule: __device__ globals)
__device__ __align__(16) float g_xg[(size_t)BB*TT*GG];   // 1 GiB: x@Wi^T + bi
__device__ __align__(16) float g_tg[BB*HH];              // topic gate bias
__device__ __align__(16) float g_hb[2][BB*HH];           // double-buffered h
__device__ unsigned g_bar_count = 0;
__device__ volatile unsigned g_bar_gen = 0;

// Packed fp32x2 FMA (Blackwell): d = a*b + d per 32-bit half.
__device__ __forceinline__ float2 ffma2(float2 d, float2 a, float2 b) {
    asm("fma.rn.f32x2 %0, %1, %2, %0;"
        : "+l"(reinterpret_cast<unsigned long long&>(d))
        : "l"(reinterpret_cast<unsigned long long&>(a)),
          "l"(reinterpret_cast<unsigned long long&>(b)));
    return d;
}

// ---------------------------------------------------------------- tg = topic @ Wt^T + bt
__global__ void k_tg(const float* __restrict__ topic, const float* __restrict__ Wt,
                     const float* __restrict__ bt) {
    __shared__ float ts[TOPN];
    int b = blockIdx.y;
    int j = blockIdx.x * 128 + threadIdx.x;
    ts[threadIdx.x]       = topic[b*TOPN + threadIdx.x];
    ts[threadIdx.x + 128] = topic[b*TOPN + threadIdx.x + 128];
    __syncthreads();
    const float4* w = (const float4*)(Wt + (size_t)j * TOPN);
    float acc = bt[j];
#pragma unroll
    for (int k = 0; k < TOPN/4; k++) {
        float4 wv = w[k];
        acc += ts[4*k+0]*wv.x + ts[4*k+1]*wv.y + ts[4*k+2]*wv.z + ts[4*k+3]*wv.w;
    }
    g_tg[b*HH + j] = acc;
}

// ---------------------------------------------------------------- xg = x @ Wi^T + bi
__global__ void __launch_bounds__(256) k_xg(const float* __restrict__ x,
                                            const float* __restrict__ Wi,
                                            const float* __restrict__ bi) {
    __shared__ float  xs[16][132];
    __shared__ float2 ws2[16][130];
    int m0 = blockIdx.y * 128;
    int n0 = blockIdx.x * 128;
    int tid = threadIdx.x;
    int tr = tid >> 4;
    int tc = tid & 15;
    float2 acc2[4][8];
#pragma unroll
    for (int p = 0; p < 4; p++)
#pragma unroll
        for (int v = 0; v < 8; v++) acc2[p][v] = make_float2(0.f, 0.f);

    for (int k0 = 0; k0 < II; k0 += 16) {
#pragma unroll
        for (int i = 0; i < 8; i++) {
            int lin = tid + i*256;
            int r = lin >> 4, kk = lin & 15;
            xs[kk][r] = x[(size_t)(m0 + r)*II + k0 + kk];
            float w = Wi[(size_t)(n0 + r)*II + k0 + kk];
            ws2[kk][r] = make_float2(w, w);
        }
        __syncthreads();
#pragma unroll
        for (int kk = 0; kk < 16; kk++) {
            float4 aA = *(const float4*)&xs[kk][tr*4];
            float4 aB = *(const float4*)&xs[kk][64 + tr*4];
            float2 ap[4] = { make_float2(aA.x, aA.y), make_float2(aA.z, aA.w),
                             make_float2(aB.x, aB.y), make_float2(aB.z, aB.w) };
            float4 wA = *(const float4*)&ws2[kk][tc*4];
            float4 wB = *(const float4*)&ws2[kk][tc*4 + 2];
            float4 wC = *(const float4*)&ws2[kk][64 + tc*4];
            float4 wD = *(const float4*)&ws2[kk][64 + tc*4 + 2];
            float2 wd[8] = { make_float2(wA.x, wA.y), make_float2(wA.z, wA.w),
                             make_float2(wB.x, wB.y), make_float2(wB.z, wB.w),
                             make_float2(wC.x, wC.y), make_float2(wC.z, wC.w),
                             make_float2(wD.x, wD.y), make_float2(wD.z, wD.w) };
#pragma unroll
            for (int p = 0; p < 4; p++)
#pragma unroll
                for (int v = 0; v < 8; v++)
                    acc2[p][v] = ffma2(acc2[p][v], ap[p], wd[v]);
        }
        __syncthreads();
    }
    float bv[8];
#pragma unroll
    for (int v = 0; v < 8; v++) {
        int n = n0 + ((v < 4) ? (tc*4 + v) : (64 + tc*4 + v - 4));
        bv[v] = bi[n];
    }
#pragma unroll
    for (int p = 0; p < 4; p++) {
        int m = m0 + ((p < 2) ? (tr*4 + 2*p) : (64 + tr*4 + 2*(p - 2)));
#pragma unroll
        for (int v = 0; v < 8; v++) {
            int n = n0 + ((v < 4) ? (tc*4 + v) : (64 + tc*4 + v - 4));
            g_xg[(size_t)m*GG + n]       = acc2[p][v].x + bv[v];
            g_xg[(size_t)(m+1)*GG + n]   = acc2[p][v].y + bv[v];
        }
    }
}

// ---------------------------------------------------------------- grid barrier
__device__ __forceinline__ void grid_bar() {
    __syncthreads();
    if (threadIdx.x == 0) {
        __threadfence();
        unsigned gen = g_bar_gen;
        if (atomicAdd(&g_bar_count, 1u) == NCTA - 1) {
            g_bar_count = 0;
            __threadfence();
            g_bar_gen = gen + 1;
        } else {
            while (g_bar_gen == gen) __nanosleep(16);
            __threadfence();
        }
    }
    __syncthreads();
}

// ---------------------------------------------------------------- persistent recurrence
// 128 CTAs x 256 thr. CTA c owns 8 h-cols (j0=c*8) x 4 gates = 32 gate rows.
// Wh slice (32x1024, pre-paired float2) resident in SMEM. h streamed through a
// double-buffered, LDG-prefetched smem tile. f32x2 packs 2 N-values per FMA.
__global__ void __launch_bounds__(256) k_rec(const float* __restrict__ Wh,
                                             const float* __restrict__ bh,
                                             const float* __restrict__ h0,
                                             const float* __restrict__ c0,
                                             float* __restrict__ out) {
    extern __shared__ char smraw[];
    float2 (*wpairs)[16]    = (float2(*)[16])smraw;                       // [k][npair]
    float2 (*hs2)[16][66]   = (float2(*)[16][66])(smraw + SM_WP_BYTES);   // [buf][kk][m]
    float  (*ga)[66]        = (float(*)[66])(smraw + SM_WP_BYTES + SM_HS_BYTES); // [n][b]

    const int tid = threadIdx.x;
    const int c = blockIdx.x;
    const int j0 = c * 8;

    // ---- GEMM thread mapping
    const int mg = tid >> 3;          // 0..31 -> m in {2mg, 2mg+1}
    const int np = tid & 7;           // 0..7  -> npairs {2np, 2np+1} (n-local 4np..4np+3)
    // ---- h-stream loader mapping
    const int ml = tid >> 2;          // 0..63
    const int ql = tid & 3;           // 0..3  -> k sub-offset ql*4
    // ---- elementwise mapping (2 cells)
    const int b_e  = tid >> 2;
    const int jl_e = (tid & 3) * 2;
    const int jg0  = j0 + jl_e;

    // ---- stage h0 (this CTA's slice of the global h buffer)
#pragma unroll
    for (int i = 0; i < 2; i++) {
        int idx = c*512 + tid + i*256;
        g_hb[0][idx] = h0[idx];
    }

    // ---- preload Wh slice into smem as (w_n0, w_n1) pairs
    {
        const int p = tid & 15;                 // npair 0..15
        const int n0l = 2*p, n1l = 2*p + 1;
        const float* wr0 = Wh + (size_t)((n0l >> 3)*HH + j0 + (n0l & 7)) * HH;
        const float* wr1 = Wh + (size_t)((n1l >> 3)*HH + j0 + (n1l & 7)) * HH;
        for (int k = (tid >> 4); k < HH; k += 16)
            wpairs[k][p] = make_float2(__ldg(wr0 + k), __ldg(wr1 + k));
    }

    // ---- per-cell constants
    float cr0 = c0[b_e*HH + jg0];
    float cr1 = c0[b_e*HH + jg0 + 1];
    const float tg0 = g_tg[b_e*HH + jg0];
    const float tg1 = g_tg[b_e*HH + jg0 + 1];
    float bhv[4][2];
#pragma unroll
    for (int g = 0; g < 4; g++) {
        bhv[g][0] = bh[g*HH + jg0];
        bhv[g][1] = bh[g*HH + jg0 + 1];
    }

    grid_bar();   // h0 + wpairs of all CTAs ready

    for (int t = 0; t < TT; t++) {
        const int rb = t & 1, wb = rb ^ 1;
        const float* hbase = g_hb[rb];

        // prefetch xg for this step's elementwise (overlaps entire GEMM)
        const size_t xb = ((size_t)b_e*TT + t)*GG + jg0;
        float x_i0 = __ldcs(&g_xg[xb]);
        float x_f0 = __ldcs(&g_xg[xb + HH]);
        float x_c0 = __ldcs(&g_xg[xb + 2*(size_t)HH]);
        float x_o0 = __ldcs(&g_xg[xb + 3*(size_t)HH]);
        float x_i1 = __ldcs(&g_xg[xb + 1]);
        float x_f1 = __ldcs(&g_xg[xb + 1 + HH]);
        float x_c1 = __ldcs(&g_xg[xb + 1 + 2*(size_t)HH]);
        float x_o1 = __ldcs(&g_xg[xb + 1 + 3*(size_t)HH]);

        float2 acc00 = make_float2(0.f,0.f), acc01 = make_float2(0.f,0.f);
        float2 acc10 = make_float2(0.f,0.f), acc11 = make_float2(0.f,0.f);

        // chunk 0 -> buffer 0
        {
            float4 hp = __ldcg((const float4*)(hbase + ml*HH + ql*4));
            hs2[0][ql*4+0][ml] = make_float2(hp.x, hp.x);
            hs2[0][ql*4+1][ml] = make_float2(hp.y, hp.y);
            hs2[0][ql*4+2][ml] = make_float2(hp.z, hp.z);
            hs2[0][ql*4+3][ml] = make_float2(hp.w, hp.w);
        }
        __syncthreads();

        int buf = 0;
        for (int kc = 0; kc < 64; kc++) {
            float4 hp;
            const bool more = (kc < 63);
            if (more) hp = __ldcg((const float4*)(hbase + ml*HH + (kc+1)*16 + ql*4));
#pragma unroll
            for (int kk = 0; kk < 16; kk++) {
                float4 hv = *(const float4*)&hs2[buf][kk][2*mg];
                float4 wv = *(const float4*)&wpairs[kc*16 + kk][2*np];
                float2 h0v = make_float2(hv.x, hv.y), h1v = make_float2(hv.z, hv.w);
                float2 w0v = make_float2(wv.x, wv.y), w1v = make_float2(wv.z, wv.w);
                acc00 = ffma2(acc00, h0v, w0v);
                acc01 = ffma2(acc01, h0v, w1v);
                acc10 = ffma2(acc10, h1v, w0v);
                acc11 = ffma2(acc11, h1v, w1v);
            }
            if (more) {
                int nb = buf ^ 1;
                hs2[nb][ql*4+0][ml] = make_float2(hp.x, hp.x);
                hs2[nb][ql*4+1][ml] = make_float2(hp.y, hp.y);
                hs2[nb][ql*4+2][ml] = make_float2(hp.z, hp.z);
                hs2[nb][ql*4+3][ml] = make_float2(hp.w, hp.w);
            }
            __syncthreads();
            buf ^= 1;
        }

        // scatter gates: ga[n-local][b]
        {
            int m0r = 2*mg;
            ga[4*np + 0][m0r]     = acc00.x;
            ga[4*np + 1][m0r]     = acc00.y;
            ga[4*np + 2][m0r]     = acc01.x;
            ga[4*np + 3][m0r]     = acc01.y;
            ga[4*np + 0][m0r + 1] = acc10.x;
            ga[4*np + 1][m0r + 1] = acc10.y;
            ga[4*np + 2][m0r + 1] = acc11.x;
            ga[4*np + 3][m0r + 1] = acc11.y;
        }
        __syncthreads();

        // elementwise for 2 owned cells
        {
            float gi0 = ga[     jl_e][b_e] + x_i0 + bhv[0][0] + tg0;
            float gf0 = ga[ 8 + jl_e][b_e] + x_f0 + bhv[1][0] + tg0;
            float gc0 = ga[16 + jl_e][b_e] + x_c0 + bhv[2][0];
            float go0 = ga[24 + jl_e][b_e] + x_o0 + bhv[3][0];
            float gi1 = ga[     jl_e + 1][b_e] + x_i1 + bhv[0][1] + tg1;
            float gf1 = ga[ 8 + jl_e + 1][b_e] + x_f1 + bhv[1][1] + tg1;
            float gc1 = ga[16 + jl_e + 1][b_e] + x_c1 + bhv[2][1];
            float go1 = ga[24 + jl_e + 1][b_e] + x_o1 + bhv[3][1];

            float ig0 = 1.f/(1.f + expf(-gi0)), fg0 = 1.f/(1.f + expf(-gf0));
            float cg0 = tanhf(gc0),             og0 = 1.f/(1.f + expf(-go0));
            float cy0 = fg0*cr0 + ig0*cg0;
            float hy0 = og0 * tanhf(cy0);
            float ig1 = 1.f/(1.f + expf(-gi1)), fg1 = 1.f/(1.f + expf(-gf1));
            float cg1 = tanhf(gc1),             og1 = 1.f/(1.f + expf(-go1));
            float cy1 = fg1*cr1 + ig1*cg1;
            float hy1 = og1 * tanhf(cy1);
            cr0 = cy0; cr1 = cy1;

            g_hb[wb][b_e*HH + jg0]     = hy0;
            g_hb[wb][b_e*HH + jg0 + 1] = hy1;
            size_t ob = ((size_t)b_e*TT + t)*HH + jg0;
            out[ob]     = hy0;
            out[ob + 1] = hy1;
            if (t == TT - 1) {
                const size_t HN = (size_t)BB*TT*HH;
                out[HN + b_e*HH + jg0]     = hy0;
                out[HN + b_e*HH + jg0 + 1] = hy1;
                out[HN + (size_t)BB*HH + b_e*HH + jg0]     = cy0;
                out[HN + (size_t)BB*HH + b_e*HH + jg0 + 1] = cy1;
            }
        }
        if (t < TT - 1) grid_bar();
    }
}

// ----------------------------------------------------------------
extern "C" void kernel_launch(void* const* d_in, const int* in_sizes, int n_in,
                              void* d_out, int out_size) {
    const float* x     = (const float*)d_in[0];
    const float* h0    = (const float*)d_in[1];
    const float* c0    = (const float*)d_in[2];
    const float* topic = (const float*)d_in[3];
    const float* Wi    = (const float*)d_in[4];
    const float* bi    = (const float*)d_in[5];
    const float* Wh    = (const float*)d_in[6];
    const float* bh    = (const float*)d_in[7];
    const float* Wt    = (const float*)d_in[8];
    const float* bt    = (const float*)d_in[9];
    float* out = (float*)d_out;

    cudaFuncSetAttribute(k_rec, cudaFuncAttributeMaxDynamicSharedMemorySize, SM_REC_TOTAL);

    k_tg<<<dim3(8, 64), 128>>>(topic, Wt, bt);
    k_xg<<<dim3(GG/128, (BB*TT)/128), 256>>>(x, Wi, bi);   // (32, 512)
    k_rec<<<NCTA, 256, SM_REC_TOTAL>>>(Wh, bh, h0, c0, out);
}

// round 5
// speedup vs baseline: 1.3042x; 1.2378x over previous
#include <cuda_runtime.h>
#include <math.h>

#define BB 64
#define TT 1024
#define II 512
#define HH 1024
#define GG (4*HH)   // 4096
#define TOPN 256
#define NCTA 128

// Dynamic smem carve for k_rec
#define SM_WS_BYTES (1024*36*4)        // ws[1024][36]       = 147456 (Wh slice, scalar, padded)
#define SM_HS_BYTES (2*4*16*68*4)      // hs[2][4][16][68]   = 34816  (h stream, dbl-buffered)
#define SM_PS_BYTES (4*32*68*4)        // ps[4][32][68]      = 34816  (k-split partials)
#define SM_REC_TOTAL (SM_WS_BYTES + SM_HS_BYTES + SM_PS_BYTES)   // 217088

// Scratch (allocation-free rule: __device__ globals)
__device__ __align__(16) float g_xg[(size_t)BB*TT*GG];   // 1 GiB: x@Wi^T + bi
__device__ __align__(16) float g_tg[BB*HH];              // topic gate bias
__device__ __align__(16) float g_hb[2][BB*HH];           // double-buffered h
__device__ unsigned g_bar_count = 0;
__device__ volatile unsigned g_bar_gen = 0;

// Packed fp32x2 FMA (Blackwell): d = a*b + d per 32-bit half.
__device__ __forceinline__ float2 ffma2(float2 d, float2 a, float2 b) {
    asm("fma.rn.f32x2 %0, %1, %2, %0;"
        : "+l"(reinterpret_cast<unsigned long long&>(d))
        : "l"(reinterpret_cast<unsigned long long&>(a)),
          "l"(reinterpret_cast<unsigned long long&>(b)));
    return d;
}

// ---------------------------------------------------------------- tg = topic @ Wt^T + bt
__global__ void k_tg(const float* __restrict__ topic, const float* __restrict__ Wt,
                     const float* __restrict__ bt) {
    __shared__ float ts[TOPN];
    int b = blockIdx.y;
    int j = blockIdx.x * 128 + threadIdx.x;
    ts[threadIdx.x]       = topic[b*TOPN + threadIdx.x];
    ts[threadIdx.x + 128] = topic[b*TOPN + threadIdx.x + 128];
    __syncthreads();
    const float4* w = (const float4*)(Wt + (size_t)j * TOPN);
    float acc = bt[j];
#pragma unroll
    for (int k = 0; k < TOPN/4; k++) {
        float4 wv = w[k];
        acc += ts[4*k+0]*wv.x + ts[4*k+1]*wv.y + ts[4*k+2]*wv.z + ts[4*k+3]*wv.w;
    }
    g_tg[b*HH + j] = acc;
}

// ---------------------------------------------------------------- xg = x @ Wi^T + bi
__global__ void __launch_bounds__(256) k_xg(const float* __restrict__ x,
                                            const float* __restrict__ Wi,
                                            const float* __restrict__ bi) {
    __shared__ float  xs[16][132];
    __shared__ float2 ws2[16][130];
    int m0 = blockIdx.y * 128;
    int n0 = blockIdx.x * 128;
    int tid = threadIdx.x;
    int tr = tid >> 4;
    int tc = tid & 15;
    float2 acc2[4][8];
#pragma unroll
    for (int p = 0; p < 4; p++)
#pragma unroll
        for (int v = 0; v < 8; v++) acc2[p][v] = make_float2(0.f, 0.f);

    for (int k0 = 0; k0 < II; k0 += 16) {
#pragma unroll
        for (int i = 0; i < 8; i++) {
            int lin = tid + i*256;
            int r = lin >> 4, kk = lin & 15;
            xs[kk][r] = x[(size_t)(m0 + r)*II + k0 + kk];
            float w = Wi[(size_t)(n0 + r)*II + k0 + kk];
            ws2[kk][r] = make_float2(w, w);
        }
        __syncthreads();
#pragma unroll
        for (int kk = 0; kk < 16; kk++) {
            float4 aA = *(const float4*)&xs[kk][tr*4];
            float4 aB = *(const float4*)&xs[kk][64 + tr*4];
            float2 ap[4] = { make_float2(aA.x, aA.y), make_float2(aA.z, aA.w),
                             make_float2(aB.x, aB.y), make_float2(aB.z, aB.w) };
            float4 wA = *(const float4*)&ws2[kk][tc*4];
            float4 wB = *(const float4*)&ws2[kk][tc*4 + 2];
            float4 wC = *(const float4*)&ws2[kk][64 + tc*4];
            float4 wD = *(const float4*)&ws2[kk][64 + tc*4 + 2];
            float2 wd[8] = { make_float2(wA.x, wA.y), make_float2(wA.z, wA.w),
                             make_float2(wB.x, wB.y), make_float2(wB.z, wB.w),
                             make_float2(wC.x, wC.y), make_float2(wC.z, wC.w),
                             make_float2(wD.x, wD.y), make_float2(wD.z, wD.w) };
#pragma unroll
            for (int p = 0; p < 4; p++)
#pragma unroll
                for (int v = 0; v < 8; v++)
                    acc2[p][v] = ffma2(acc2[p][v], ap[p], wd[v]);
        }
        __syncthreads();
    }
    float bv[8];
#pragma unroll
    for (int v = 0; v < 8; v++) {
        int n = n0 + ((v < 4) ? (tc*4 + v) : (64 + tc*4 + v - 4));
        bv[v] = bi[n];
    }
#pragma unroll
    for (int p = 0; p < 4; p++) {
        int m = m0 + ((p < 2) ? (tr*4 + 2*p) : (64 + tr*4 + 2*(p - 2)));
#pragma unroll
        for (int v = 0; v < 8; v++) {
            int n = n0 + ((v < 4) ? (tc*4 + v) : (64 + tc*4 + v - 4));
            g_xg[(size_t)m*GG + n]       = acc2[p][v].x + bv[v];
            g_xg[(size_t)(m+1)*GG + n]   = acc2[p][v].y + bv[v];
        }
    }
}

// ---------------------------------------------------------------- grid barrier
__device__ __forceinline__ void grid_bar() {
    __syncthreads();
    if (threadIdx.x == 0) {
        __threadfence();
        unsigned gen = g_bar_gen;
        if (atomicAdd(&g_bar_count, 1u) == NCTA - 1) {
            g_bar_count = 0;
            __threadfence();
            g_bar_gen = gen + 1;
        } else {
            while (g_bar_gen == gen) __nanosleep(16);
            __threadfence();
        }
    }
    __syncthreads();
}

// ---------------------------------------------------------------- persistent recurrence
// 128 CTAs x 256 thr. CTA owns 8 h-cols (32 gate-rows). Intra-CTA K-split x4:
// group g (64 thr) covers k in [g*256,(g+1)*256), thread tile 8m x 4n, f32x2
// packs adjacent m-pairs (no operand duplication in smem; w duplicated in regs).
__global__ void __launch_bounds__(256) k_rec(const float* __restrict__ Wh,
                                             const float* __restrict__ bh,
                                             const float* __restrict__ h0,
                                             const float* __restrict__ c0,
                                             float* __restrict__ out) {
    extern __shared__ char smraw[];
    float (*ws)[36]         = (float(*)[36])smraw;                          // [k][nl]
    float (*hs)[4][16][68]  = (float(*)[4][16][68])(smraw + SM_WS_BYTES);   // [buf][g][kk][m]
    float (*ps)[32][68]     = (float(*)[32][68])(smraw + SM_WS_BYTES + SM_HS_BYTES); // [g][nl][b]

    const int tid  = threadIdx.x;
    const int c    = blockIdx.x;
    const int j0   = c * 8;
    const int g    = tid >> 6;           // k-split group 0..3
    const int lane = tid & 63;
    const int m0   = (lane & 7) * 8;     // 8 m-values (4 float2 pairs)
    const int nl0  = (lane >> 3) * 4;    // 4 n-values
    const int kb0  = g * 256;

    // ---- stage h0 slice
#pragma unroll
    for (int i = 0; i < 2; i++) {
        int idx = c*512 + tid + i*256;
        g_hb[0][idx] = h0[idx];
    }

    // ---- upload Wh slice -> ws[k][nl] (scalar, transposed)
    {
        const int nl = tid >> 3;         // 0..31
        const int kq = tid & 7;          // 0..7
        const float* wr = Wh + (size_t)((nl >> 3)*HH + j0 + (nl & 7)) * HH;
#pragma unroll 4
        for (int i = 0; i < 32; i++) {
            int k = i*32 + kq*4;
            float4 w4 = __ldg((const float4*)(wr + k));
            ws[k  ][nl] = w4.x;
            ws[k+1][nl] = w4.y;
            ws[k+2][nl] = w4.z;
            ws[k+3][nl] = w4.w;
        }
    }

    // ---- elementwise constants (2 cells per thread)
    const int b_e  = tid >> 2;
    const int jl_e = (tid & 3) * 2;
    const int jg0  = j0 + jl_e;
    float cr0 = c0[b_e*HH + jg0];
    float cr1 = c0[b_e*HH + jg0 + 1];
    const float tg0 = g_tg[b_e*HH + jg0];
    const float tg1 = g_tg[b_e*HH + jg0 + 1];
    float bhv[4][2];
#pragma unroll
    for (int gt = 0; gt < 4; gt++) {
        bhv[gt][0] = bh[gt*HH + jg0];
        bhv[gt][1] = bh[gt*HH + jg0 + 1];
    }

    grid_bar();   // h0 + ws of all CTAs ready

    for (int t = 0; t < TT; t++) {
        const int rb = t & 1, wb = rb ^ 1;
        const float* hbase = g_hb[rb];

        // xg prefetch for elementwise (overlaps whole GEMM)
        const size_t xb = ((size_t)b_e*TT + t)*GG + jg0;
        float x_i0 = __ldcs(&g_xg[xb]);
        float x_f0 = __ldcs(&g_xg[xb + HH]);
        float x_c0 = __ldcs(&g_xg[xb + 2*(size_t)HH]);
        float x_o0 = __ldcs(&g_xg[xb + 3*(size_t)HH]);
        float x_i1 = __ldcs(&g_xg[xb + 1]);
        float x_f1 = __ldcs(&g_xg[xb + 1 + HH]);
        float x_c1 = __ldcs(&g_xg[xb + 1 + 2*(size_t)HH]);
        float x_o1 = __ldcs(&g_xg[xb + 1 + 3*(size_t)HH]);

        float2 acc[4][4];   // [j = n offset][p = m pair]
#pragma unroll
        for (int j = 0; j < 4; j++)
#pragma unroll
            for (int p = 0; p < 4; p++) acc[j][p] = make_float2(0.f, 0.f);

        float4 pf0, pf1, pf2, pf3;
        const float* hrow = hbase + lane*HH + kb0;
        // chunk 0
        pf0 = __ldcg((const float4*)(hrow));
        pf1 = __ldcg((const float4*)(hrow + 4));
        pf2 = __ldcg((const float4*)(hrow + 8));
        pf3 = __ldcg((const float4*)(hrow + 12));
        hs[0][g][ 0][lane]=pf0.x; hs[0][g][ 1][lane]=pf0.y; hs[0][g][ 2][lane]=pf0.z; hs[0][g][ 3][lane]=pf0.w;
        hs[0][g][ 4][lane]=pf1.x; hs[0][g][ 5][lane]=pf1.y; hs[0][g][ 6][lane]=pf1.z; hs[0][g][ 7][lane]=pf1.w;
        hs[0][g][ 8][lane]=pf2.x; hs[0][g][ 9][lane]=pf2.y; hs[0][g][10][lane]=pf2.z; hs[0][g][11][lane]=pf2.w;
        hs[0][g][12][lane]=pf3.x; hs[0][g][13][lane]=pf3.y; hs[0][g][14][lane]=pf3.z; hs[0][g][15][lane]=pf3.w;
        __syncthreads();

        int buf = 0;
        for (int cc = 0; cc < 16; cc++) {
            const bool more = (cc < 15);
            if (more) {
                const float* p = hrow + (cc + 1)*16;
                pf0 = __ldcg((const float4*)(p));
                pf1 = __ldcg((const float4*)(p + 4));
                pf2 = __ldcg((const float4*)(p + 8));
                pf3 = __ldcg((const float4*)(p + 12));
            }
            const int kb = kb0 + cc*16;
#pragma unroll
            for (int kk = 0; kk < 16; kk++) {
                float4 h01 = *(const float4*)&hs[buf][g][kk][m0];
                float4 h23 = *(const float4*)&hs[buf][g][kk][m0 + 4];
                float4 wv  = *(const float4*)&ws[kb + kk][nl0];
                float2 hp[4] = { make_float2(h01.x, h01.y), make_float2(h01.z, h01.w),
                                 make_float2(h23.x, h23.y), make_float2(h23.z, h23.w) };
                float2 wd[4] = { make_float2(wv.x, wv.x), make_float2(wv.y, wv.y),
                                 make_float2(wv.z, wv.z), make_float2(wv.w, wv.w) };
#pragma unroll
                for (int j = 0; j < 4; j++)
#pragma unroll
                    for (int p = 0; p < 4; p++)
                        acc[j][p] = ffma2(acc[j][p], hp[p], wd[j]);
            }
            if (more) {
                const int nb = buf ^ 1;
                hs[nb][g][ 0][lane]=pf0.x; hs[nb][g][ 1][lane]=pf0.y; hs[nb][g][ 2][lane]=pf0.z; hs[nb][g][ 3][lane]=pf0.w;
                hs[nb][g][ 4][lane]=pf1.x; hs[nb][g][ 5][lane]=pf1.y; hs[nb][g][ 6][lane]=pf1.z; hs[nb][g][ 7][lane]=pf1.w;
                hs[nb][g][ 8][lane]=pf2.x; hs[nb][g][ 9][lane]=pf2.y; hs[nb][g][10][lane]=pf2.z; hs[nb][g][11][lane]=pf2.w;
                hs[nb][g][12][lane]=pf3.x; hs[nb][g][13][lane]=pf3.y; hs[nb][g][14][lane]=pf3.z; hs[nb][g][15][lane]=pf3.w;
            }
            __syncthreads();
            buf ^= 1;
        }

        // write K-split partials: ps[g][nl][m]
#pragma unroll
        for (int j = 0; j < 4; j++) {
            *(float4*)&ps[g][nl0 + j][m0]     = make_float4(acc[j][0].x, acc[j][0].y, acc[j][1].x, acc[j][1].y);
            *(float4*)&ps[g][nl0 + j][m0 + 4] = make_float4(acc[j][2].x, acc[j][2].y, acc[j][3].x, acc[j][3].y);
        }
        __syncthreads();

        // elementwise for 2 owned cells (sum the 4 k-split partials per gate)
        {
            float s[4][2];
#pragma unroll
            for (int gt = 0; gt < 4; gt++) {
#pragma unroll
                for (int d = 0; d < 2; d++) {
                    int n = gt*8 + jl_e + d;
                    s[gt][d] = ps[0][n][b_e] + ps[1][n][b_e] + ps[2][n][b_e] + ps[3][n][b_e];
                }
            }
            float gi0 = s[0][0] + x_i0 + bhv[0][0] + tg0;
            float gf0 = s[1][0] + x_f0 + bhv[1][0] + tg0;
            float gc0 = s[2][0] + x_c0 + bhv[2][0];
            float go0 = s[3][0] + x_o0 + bhv[3][0];
            float gi1 = s[0][1] + x_i1 + bhv[0][1] + tg1;
            float gf1 = s[1][1] + x_f1 + bhv[1][1] + tg1;
            float gc1 = s[2][1] + x_c1 + bhv[2][1];
            float go1 = s[3][1] + x_o1 + bhv[3][1];

            float ig0 = 1.f/(1.f + expf(-gi0)), fg0 = 1.f/(1.f + expf(-gf0));
            float cg0 = tanhf(gc0),             og0 = 1.f/(1.f + expf(-go0));
            float cy0 = fg0*cr0 + ig0*cg0;
            float hy0 = og0 * tanhf(cy0);
            float ig1 = 1.f/(1.f + expf(-gi1)), fg1 = 1.f/(1.f + expf(-gf1));
            float cg1 = tanhf(gc1),             og1 = 1.f/(1.f + expf(-go1));
            float cy1 = fg1*cr1 + ig1*cg1;
            float hy1 = og1 * tanhf(cy1);
            cr0 = cy0; cr1 = cy1;

            g_hb[wb][b_e*HH + jg0]     = hy0;
            g_hb[wb][b_e*HH + jg0 + 1] = hy1;
            size_t ob = ((size_t)b_e*TT + t)*HH + jg0;
            out[ob]     = hy0;
            out[ob + 1] = hy1;
            if (t == TT - 1) {
                const size_t HN = (size_t)BB*TT*HH;
                out[HN + b_e*HH + jg0]     = hy0;
                out[HN + b_e*HH + jg0 + 1] = hy1;
                out[HN + (size_t)BB*HH + b_e*HH + jg0]     = cy0;
                out[HN + (size_t)BB*HH + b_e*HH + jg0 + 1] = cy1;
            }
        }
        if (t < TT - 1) grid_bar();
    }
}

// ----------------------------------------------------------------
extern "C" void kernel_launch(void* const* d_in, const int* in_sizes, int n_in,
                              void* d_out, int out_size) {
    const float* x     = (const float*)d_in[0];
    const float* h0    = (const float*)d_in[1];
    const float* c0    = (const float*)d_in[2];
    const float* topic = (const float*)d_in[3];
    const float* Wi    = (const float*)d_in[4];
    const float* bi    = (const float*)d_in[5];
    const float* Wh    = (const float*)d_in[6];
    const float* bh    = (const float*)d_in[7];
    const float* Wt    = (const float*)d_in[8];
    const float* bt    = (const float*)d_in[9];
    float* out = (float*)d_out;

    cudaFuncSetAttribute(k_rec, cudaFuncAttributeMaxDynamicSharedMemorySize, SM_REC_TOTAL);

    k_tg<<<dim3(8, 64), 128>>>(topic, Wt, bt);
    k_xg<<<dim3(GG/128, (BB*TT)/128), 256>>>(x, Wi, bi);   // (32, 512)
    k_rec<<<NCTA, 256, SM_REC_TOTAL>>>(Wh, bh, h0, c0, out);
}

// round 7
// speedup vs baseline: 1.5548x; 1.1921x over previous
#include <cuda_runtime.h>
#include <math.h>

#define BB 64
#define TT 1024
#define II 512
#define HH 1024
#define GG (4*HH)   // 4096
#define TOPN 256
#define NCTA 128

// Dynamic smem carve for k_rec
#define SM_WS_BYTES (1024*36*4)          // ws[1024][36]        = 147456 (Wh slice, scalar; 16B-aligned rows)
#define SM_HS_BYTES (2*4*16*68*4)        // hs[2][4][16][68]    =  34816 (h stream, holed layout)
#define SM_PS_BYTES (4*32*68*4)          // ps[4][32][68]       =  34816 (k-split partials)
#define SM_REC_TOTAL (SM_WS_BYTES + SM_HS_BYTES + SM_PS_BYTES)  // 217088 (proven OK in R4)

// Scratch (allocation-free rule: __device__ globals)
__device__ __align__(16) float g_xg[(size_t)BB*TT*GG];   // 1 GiB: x@Wi^T + bi
__device__ __align__(16) float g_hb[2][BB*HH];           // double-buffered h
__device__ unsigned g_bar_count = 0;
__device__ volatile unsigned g_bar_gen = 0;

// Packed fp32x2 FMA (Blackwell): d = a*b + d per 32-bit half.
__device__ __forceinline__ float2 ffma2(float2 d, float2 a, float2 b) {
    asm("fma.rn.f32x2 %0, %1, %2, %0;"
        : "+l"(reinterpret_cast<unsigned long long&>(d))
        : "l"(reinterpret_cast<unsigned long long&>(a)),
          "l"(reinterpret_cast<unsigned long long&>(b)));
    return d;
}

// ---------------------------------------------------------------- xg = x @ Wi^T + bi
__global__ void __launch_bounds__(256) k_xg(const float* __restrict__ x,
                                            const float* __restrict__ Wi,
                                            const float* __restrict__ bi) {
    __shared__ float  xs[16][132];
    __shared__ float2 ws2[16][130];
    int m0 = blockIdx.y * 128;
    int n0 = blockIdx.x * 128;
    int tid = threadIdx.x;
    int tr = tid >> 4;
    int tc = tid & 15;
    float2 acc2[4][8];
#pragma unroll
    for (int p = 0; p < 4; p++)
#pragma unroll
        for (int v = 0; v < 8; v++) acc2[p][v] = make_float2(0.f, 0.f);

    for (int k0 = 0; k0 < II; k0 += 16) {
#pragma unroll
        for (int i = 0; i < 8; i++) {
            int lin = tid + i*256;
            int r = lin >> 4, kk = lin & 15;
            xs[kk][r] = x[(size_t)(m0 + r)*II + k0 + kk];
            float w = Wi[(size_t)(n0 + r)*II + k0 + kk];
            ws2[kk][r] = make_float2(w, w);
        }
        __syncthreads();
#pragma unroll
        for (int kk = 0; kk < 16; kk++) {
            float4 aA = *(const float4*)&xs[kk][tr*4];
            float4 aB = *(const float4*)&xs[kk][64 + tr*4];
            float2 ap[4] = { make_float2(aA.x, aA.y), make_float2(aA.z, aA.w),
                             make_float2(aB.x, aB.y), make_float2(aB.z, aB.w) };
            float4 wA = *(const float4*)&ws2[kk][tc*4];
            float4 wB = *(const float4*)&ws2[kk][tc*4 + 2];
            float4 wC = *(const float4*)&ws2[kk][64 + tc*4];
            float4 wD = *(const float4*)&ws2[kk][64 + tc*4 + 2];
            float2 wd[8] = { make_float2(wA.x, wA.y), make_float2(wA.z, wA.w),
                             make_float2(wB.x, wB.y), make_float2(wB.z, wB.w),
                             make_float2(wC.x, wC.y), make_float2(wC.z, wC.w),
                             make_float2(wD.x, wD.y), make_float2(wD.z, wD.w) };
#pragma unroll
            for (int p = 0; p < 4; p++)
#pragma unroll
                for (int v = 0; v < 8; v++)
                    acc2[p][v] = ffma2(acc2[p][v], ap[p], wd[v]);
        }
        __syncthreads();
    }
    float bv[8];
#pragma unroll
    for (int v = 0; v < 8; v++) {
        int n = n0 + ((v < 4) ? (tc*4 + v) : (64 + tc*4 + v - 4));
        bv[v] = bi[n];
    }
#pragma unroll
    for (int p = 0; p < 4; p++) {
        int m = m0 + ((p < 2) ? (tr*4 + 2*p) : (64 + tr*4 + 2*(p - 2)));
#pragma unroll
        for (int v = 0; v < 8; v++) {
            int n = n0 + ((v < 4) ? (tc*4 + v) : (64 + tc*4 + v - 4));
            g_xg[(size_t)m*GG + n]       = acc2[p][v].x + bv[v];
            g_xg[(size_t)(m+1)*GG + n]   = acc2[p][v].y + bv[v];
        }
    }
}

// ---------------------------------------------------------------- grid barrier
__device__ __forceinline__ void grid_bar() {
    __syncthreads();
    if (threadIdx.x == 0) {
        __threadfence();
        unsigned gen = g_bar_gen;
        if (atomicAdd(&g_bar_count, 1u) == NCTA - 1) {
            g_bar_count = 0;
            __threadfence();
            g_bar_gen = gen + 1;
        } else {
            while (g_bar_gen == gen) __nanosleep(16);
            __threadfence();
        }
    }
    __syncthreads();
}

// ---------------------------------------------------------------- persistent recurrence
// 128 CTAs x 256 thr. CTA owns 8 h-cols (32 gate-rows). K-split x4 (64-thr
// groups). Thread tile 8m x 4n, f32x2 over m-pairs, w duplicated in regs.
// h smem rows use a 4-float hole at m=32 so all LDS.128 are conflict-free.
__global__ void __launch_bounds__(256) k_rec(const float* __restrict__ Wh,
                                             const float* __restrict__ bh,
                                             const float* __restrict__ h0,
                                             const float* __restrict__ c0,
                                             const float* __restrict__ topic,
                                             const float* __restrict__ Wt,
                                             const float* __restrict__ bt,
                                             float* __restrict__ out) {
    extern __shared__ char smraw[];
    float (*ws)[36]         = (float(*)[36])smraw;                          // [k][nl]
    float (*hs)[4][16][68]  = (float(*)[4][16][68])(smraw + SM_WS_BYTES);   // [buf][g][kk][bIdx]
    float (*ps)[32][68]     = (float(*)[32][68])(smraw + SM_WS_BYTES + SM_HS_BYTES); // [g][nl][b]

    const int tid  = threadIdx.x;
    const int c    = blockIdx.x;
    const int j0   = c * 8;
    const int g    = tid >> 6;           // k-split group 0..3
    const int lane = tid & 63;
    const int m0   = (lane & 7) * 8;             // 8 m-values
    const int m0h  = m0 + (m0 >> 5) * 4;         // holed smem index (16B aligned)
    const int nl0  = (lane >> 3) * 4;            // 4 n-values
    const int kb0  = g * 256;
    const int mIdx = lane + (lane >> 5) * 4;     // holed store index for loader

    // ---- stage h0 slice
#pragma unroll
    for (int i = 0; i < 2; i++) {
        int idx = c*512 + tid + i*256;
        g_hb[0][idx] = h0[idx];
    }

    // ---- upload Wh slice -> ws[k][nl] (scalar, transposed)
    {
        const int nl = tid >> 3;         // 0..31
        const int kq = tid & 7;          // 0..7
        const float* wr = Wh + (size_t)((nl >> 3)*HH + j0 + (nl & 7)) * HH;
#pragma unroll 4
        for (int i = 0; i < 32; i++) {
            int k = i*32 + kq*4;
            float4 w4 = __ldg((const float4*)(wr + k));
            ws[k  ][nl] = w4.x;
            ws[k+1][nl] = w4.y;
            ws[k+2][nl] = w4.z;
            ws[k+3][nl] = w4.w;
        }
    }

    // ---- elementwise constants (2 cells per thread)
    const int b_e  = tid >> 2;
    const int jl_e = (tid & 3) * 2;
    const int jg0  = j0 + jl_e;
    float cr0 = c0[b_e*HH + jg0];
    float cr1 = c0[b_e*HH + jg0 + 1];
    // topic gate: tg = topic @ Wt^T + bt, computed per-thread (once)
    float tg0 = bt[jg0], tg1 = bt[jg0 + 1];
    {
        const float* tp  = topic + b_e*TOPN;
        const float* wt0 = Wt + (size_t)jg0 * TOPN;
        const float* wt1 = Wt + (size_t)(jg0 + 1) * TOPN;
#pragma unroll 8
        for (int k = 0; k < TOPN; k++) {
            float tv = __ldg(tp + k);
            tg0 += tv * __ldg(wt0 + k);
            tg1 += tv * __ldg(wt1 + k);
        }
    }
    float bhv[4][2];
#pragma unroll
    for (int gt = 0; gt < 4; gt++) {
        bhv[gt][0] = bh[gt*HH + jg0];
        bhv[gt][1] = bh[gt*HH + jg0 + 1];
    }

    grid_bar();   // h0 + ws of all CTAs ready

    for (int t = 0; t < TT; t++) {
        const int rb = t & 1, wb = rb ^ 1;
        const float* hbase = g_hb[rb];

        // xg prefetch for elementwise (overlaps whole GEMM)
        const size_t xb = ((size_t)b_e*TT + t)*GG + jg0;
        float x_i0 = __ldcs(&g_xg[xb]);
        float x_f0 = __ldcs(&g_xg[xb + HH]);
        float x_c0 = __ldcs(&g_xg[xb + 2*(size_t)HH]);
        float x_o0 = __ldcs(&g_xg[xb + 3*(size_t)HH]);
        float x_i1 = __ldcs(&g_xg[xb + 1]);
        float x_f1 = __ldcs(&g_xg[xb + 1 + HH]);
        float x_c1 = __ldcs(&g_xg[xb + 1 + 2*(size_t)HH]);
        float x_o1 = __ldcs(&g_xg[xb + 1 + 3*(size_t)HH]);

        float2 acc[4][4];   // [j = n offset][p = m pair]
#pragma unroll
        for (int j = 0; j < 4; j++)
#pragma unroll
            for (int p = 0; p < 4; p++) acc[j][p] = make_float2(0.f, 0.f);

        float4 pf0, pf1, pf2, pf3;
        const float* hrow = hbase + lane*HH + kb0;
        // chunk 0
        pf0 = __ldcg((const float4*)(hrow));
        pf1 = __ldcg((const float4*)(hrow + 4));
        pf2 = __ldcg((const float4*)(hrow + 8));
        pf3 = __ldcg((const float4*)(hrow + 12));
        hs[0][g][ 0][mIdx]=pf0.x; hs[0][g][ 1][mIdx]=pf0.y; hs[0][g][ 2][mIdx]=pf0.z; hs[0][g][ 3][mIdx]=pf0.w;
        hs[0][g][ 4][mIdx]=pf1.x; hs[0][g][ 5][mIdx]=pf1.y; hs[0][g][ 6][mIdx]=pf1.z; hs[0][g][ 7][mIdx]=pf1.w;
        hs[0][g][ 8][mIdx]=pf2.x; hs[0][g][ 9][mIdx]=pf2.y; hs[0][g][10][mIdx]=pf2.z; hs[0][g][11][mIdx]=pf2.w;
        hs[0][g][12][mIdx]=pf3.x; hs[0][g][13][mIdx]=pf3.y; hs[0][g][14][mIdx]=pf3.z; hs[0][g][15][mIdx]=pf3.w;
        __syncthreads();

        int buf = 0;
        for (int cc = 0; cc < 16; cc++) {
            const bool more = (cc < 15);
            if (more) {
                const float* p = hrow + (cc + 1)*16;
                pf0 = __ldcg((const float4*)(p));
                pf1 = __ldcg((const float4*)(p + 4));
                pf2 = __ldcg((const float4*)(p + 8));
                pf3 = __ldcg((const float4*)(p + 12));
            }
            const int kb = kb0 + cc*16;
#pragma unroll
            for (int kk = 0; kk < 16; kk++) {
                float4 h01 = *(const float4*)&hs[buf][g][kk][m0h];
                float4 h23 = *(const float4*)&hs[buf][g][kk][m0h + 4];
                float4 wv  = *(const float4*)&ws[kb + kk][nl0];
                float2 hp[4] = { make_float2(h01.x, h01.y), make_float2(h01.z, h01.w),
                                 make_float2(h23.x, h23.y), make_float2(h23.z, h23.w) };
                float2 wd[4] = { make_float2(wv.x, wv.x), make_float2(wv.y, wv.y),
                                 make_float2(wv.z, wv.z), make_float2(wv.w, wv.w) };
#pragma unroll
                for (int j = 0; j < 4; j++)
#pragma unroll
                    for (int p = 0; p < 4; p++)
                        acc[j][p] = ffma2(acc[j][p], hp[p], wd[j]);
            }
            if (more) {
                const int nb = buf ^ 1;
                hs[nb][g][ 0][mIdx]=pf0.x; hs[nb][g][ 1][mIdx]=pf0.y; hs[nb][g][ 2][mIdx]=pf0.z; hs[nb][g][ 3][mIdx]=pf0.w;
                hs[nb][g][ 4][mIdx]=pf1.x; hs[nb][g][ 5][mIdx]=pf1.y; hs[nb][g][ 6][mIdx]=pf1.z; hs[nb][g][ 7][mIdx]=pf1.w;
                hs[nb][g][ 8][mIdx]=pf2.x; hs[nb][g][ 9][mIdx]=pf2.y; hs[nb][g][10][mIdx]=pf2.z; hs[nb][g][11][mIdx]=pf2.w;
                hs[nb][g][12][mIdx]=pf3.x; hs[nb][g][13][mIdx]=pf3.y; hs[nb][g][14][mIdx]=pf3.z; hs[nb][g][15][mIdx]=pf3.w;
            }
            __syncthreads();
            buf ^= 1;
        }

        // write K-split partials: ps[g][nl][m] (no hole; plain layout)
#pragma unroll
        for (int j = 0; j < 4; j++) {
            *(float4*)&ps[g][nl0 + j][m0]     = make_float4(acc[j][0].x, acc[j][0].y, acc[j][1].x, acc[j][1].y);
            *(float4*)&ps[g][nl0 + j][m0 + 4] = make_float4(acc[j][2].x, acc[j][2].y, acc[j][3].x, acc[j][3].y);
        }
        __syncthreads();

        // elementwise for 2 owned cells (sum the 4 k-split partials per gate)
        {
            float s[4][2];
#pragma unroll
            for (int gt = 0; gt < 4; gt++) {
#pragma unroll
                for (int d = 0; d < 2; d++) {
                    int n = gt*8 + jl_e + d;
                    s[gt][d] = ps[0][n][b_e] + ps[1][n][b_e] + ps[2][n][b_e] + ps[3][n][b_e];
                }
            }
            float gi0 = s[0][0] + x_i0 + bhv[0][0] + tg0;
            float gf0 = s[1][0] + x_f0 + bhv[1][0] + tg0;
            float gc0 = s[2][0] + x_c0 + bhv[2][0];
            float go0 = s[3][0] + x_o0 + bhv[3][0];
            float gi1 = s[0][1] + x_i1 + bhv[0][1] + tg1;
            float gf1 = s[1][1] + x_f1 + bhv[1][1] + tg1;
            float gc1 = s[2][1] + x_c1 + bhv[2][1];
            float go1 = s[3][1] + x_o1 + bhv[3][1];

            float ig0 = 1.f/(1.f + expf(-gi0)), fg0 = 1.f/(1.f + expf(-gf0));
            float cg0 = tanhf(gc0),             og0 = 1.f/(1.f + expf(-go0));
            float cy0 = fg0*cr0 + ig0*cg0;
            float hy0 = og0 * tanhf(cy0);
            float ig1 = 1.f/(1.f + expf(-gi1)), fg1 = 1.f/(1.f + expf(-gf1));
            float cg1 = tanhf(gc1),             og1 = 1.f/(1.f + expf(-go1));
            float cy1 = fg1*cr1 + ig1*cg1;
            float hy1 = og1 * tanhf(cy1);
            cr0 = cy0; cr1 = cy1;

            g_hb[wb][b_e*HH + jg0]     = hy0;
            g_hb[wb][b_e*HH + jg0 + 1] = hy1;
            size_t ob = ((size_t)b_e*TT + t)*HH + jg0;
            out[ob]     = hy0;
            out[ob + 1] = hy1;
            if (t == TT - 1) {
                const size_t HN = (size_t)BB*TT*HH;
                out[HN + b_e*HH + jg0]     = hy0;
                out[HN + b_e*HH + jg0 + 1] = hy1;
                out[HN + (size_t)BB*HH + b_e*HH + jg0]     = cy0;
                out[HN + (size_t)BB*HH + b_e*HH + jg0 + 1] = cy1;
            }
        }
        if (t < TT - 1) grid_bar();
    }
}

// ----------------------------------------------------------------
extern "C" void kernel_launch(void* const* d_in, const int* in_sizes, int n_in,
                              void* d_out, int out_size) {
    const float* x     = (const float*)d_in[0];
    const float* h0    = (const float*)d_in[1];
    const float* c0    = (const float*)d_in[2];
    const float* topic = (const float*)d_in[3];
    const float* Wi    = (const float*)d_in[4];
    const float* bi    = (const float*)d_in[5];
    const float* Wh    = (const float*)d_in[6];
    const float* bh    = (const float*)d_in[7];
    const float* Wt    = (const float*)d_in[8];
    const float* bt    = (const float*)d_in[9];
    float* out = (float*)d_out;

    cudaFuncSetAttribute(k_rec, cudaFuncAttributeMaxDynamicSharedMemorySize, SM_REC_TOTAL);

    k_xg<<<dim3(GG/128, (BB*TT)/128), 256>>>(x, Wi, bi);   // (32, 512)
    k_rec<<<NCTA, 256, SM_REC_TOTAL>>>(Wh, bh, h0, c0, topic, Wt, bt, out);
}